// round 5
// baseline (speedup 1.0000x reference)
#include <cuda_runtime.h>
#include <math.h>

// Problem constants (fixed by the dataset)
#define A_   16
#define SK_  2048
#define SQ_  2048
#define D_   128
#define IDM_ 128
#define RR_  3
// T_ANNEAL = 10, t_ANNEAL = 0

// ---------------------------------------------------------------------------
// Scratch (device global — no allocation allowed)
// Hash codes, padded to float4 per row.  K-codes pre-scaled by 1/R.
// ---------------------------------------------------------------------------
__device__ float4 g_code[2][A_ * SK_];       // [0] = Kc/3, [1] = Qc

// ---------------------------------------------------------------------------
// Fused kernel: fold (Wx,bx) through W[a] in-block, then compute hash codes.
// Grid: 256 blocks = (side, a, chunk-of-256-rows).  Block: 256 threads.
//   Phase 1: M[d][r] = sum_e Wx[e,d]*W[a,e,r]  (two 64-e halves, smem reduce)
//   Phase 2: c[r]    = sum_e bx[e]*W[a,e,r]    (warp 7)
//   Phase 3: one warp per row: code = tanh((x . M + c)/T) * scale
// ---------------------------------------------------------------------------
__global__ void __launch_bounds__(256) fused_code_kernel(
        const float* __restrict__ K,  const float* __restrict__ Q,
        const float* __restrict__ Wk, const float* __restrict__ bk,
        const float* __restrict__ Wq, const float* __restrict__ bq,
        const float* __restrict__ W) {
    const int chunk = blockIdx.x & 7;        // 0..7 (256 rows each)
    const int a     = (blockIdx.x >> 3) & 15;
    const int side  = blockIdx.x >> 7;       // 0 = K, 1 = Q
    const float* Wx = side ? Wq : Wk;
    const float* bx = side ? bq : bk;
    const float* X  = side ? Q  : K;

    const int t = threadIdx.x;

    __shared__ float Wsh[IDM_ * RR_];        // W[a] : [128,3]
    __shared__ float Mred[2][IDM_ * RR_];    // fold partials (two e-halves)
    __shared__ float Msh[IDM_ * RR_];        // final M, d-major [d*3+r]
    __shared__ float csh[RR_];

    // Phase 0: stage W[a]
    for (int i = t; i < IDM_ * RR_; i += 256) Wsh[i] = W[a * IDM_ * RR_ + i];
    __syncthreads();

    // Phase 1: fold.  d = t&127, half = t>>7 handles 64 e's.
    {
        const int d = t & 127;
        const int h = t >> 7;
        float a0 = 0.f, a1 = 0.f, a2 = 0.f;
#pragma unroll 8
        for (int i = 0; i < 64; i++) {
            int e = h * 64 + i;
            float w = Wx[e * D_ + d];        // coalesced; L2-broadcast across blocks
            a0 = fmaf(w, Wsh[e * 3 + 0], a0);
            a1 = fmaf(w, Wsh[e * 3 + 1], a1);
            a2 = fmaf(w, Wsh[e * 3 + 2], a2);
        }
        Mred[h][d * 3 + 0] = a0;
        Mred[h][d * 3 + 1] = a1;
        Mred[h][d * 3 + 2] = a2;
    }

    // Phase 2: bias fold on warp 7 (uses Wsh only — valid after first sync)
    if (t >= 224) {                          // one warp: lanes 0..31
        int l = t - 224;
        float c0 = 0.f, c1 = 0.f, c2 = 0.f;
#pragma unroll
        for (int e = l; e < IDM_; e += 32) {
            float b = bx[e];
            c0 = fmaf(b, Wsh[e * 3 + 0], c0);
            c1 = fmaf(b, Wsh[e * 3 + 1], c1);
            c2 = fmaf(b, Wsh[e * 3 + 2], c2);
        }
#pragma unroll
        for (int o = 16; o > 0; o >>= 1) {
            c0 += __shfl_xor_sync(0xffffffffu, c0, o);
            c1 += __shfl_xor_sync(0xffffffffu, c1, o);
            c2 += __shfl_xor_sync(0xffffffffu, c2, o);
        }
        if (l == 0) { csh[0] = c0; csh[1] = c1; csh[2] = c2; }
    }
    __syncthreads();

    // Reduce the two fold halves into Msh (grid-stride covers all 384 entries)
    for (int i = t; i < IDM_ * RR_; i += 256)
        Msh[i] = Mred[0][i] + Mred[1][i];
    __syncthreads();

    // Phase 3: codes.  8 warps, each warp does 32 consecutive rows.
    const int warp = t >> 5;
    const int lane = t & 31;

    // Per-lane M slice (d = lane*4 .. lane*4+3), hoisted out of the row loop.
    const float* M = &Msh[lane * 12];
    float4 m0 = *reinterpret_cast<const float4*>(M);
    float4 m1 = *reinterpret_cast<const float4*>(M + 4);
    float4 m2 = *reinterpret_cast<const float4*>(M + 8);
    const float c0 = csh[0], c1 = csh[1], c2 = csh[2];
    const float scale = side ? 1.0f : (1.0f / 3.0f);    // fold /R into Kc

    const int rowbase = chunk * 256 + warp * 32;
#pragma unroll 4
    for (int j = 0; j < 32; j++) {
        int row = a * SK_ + rowbase + j;
        const float4 x = reinterpret_cast<const float4*>(X)[row * (D_ / 4) + lane];

        float p0 = x.x * m0.x + x.y * m0.w + x.z * m1.z + x.w * m2.y;
        float p1 = x.x * m0.y + x.y * m1.x + x.z * m1.w + x.w * m2.z;
        float p2 = x.x * m0.z + x.y * m1.y + x.z * m2.x + x.w * m2.w;
#pragma unroll
        for (int o = 16; o > 0; o >>= 1) {
            p0 += __shfl_xor_sync(0xffffffffu, p0, o);
            p1 += __shfl_xor_sync(0xffffffffu, p1, o);
            p2 += __shfl_xor_sync(0xffffffffu, p2, o);
        }
        if (lane == 0) {
            float v0 = tanhf((p0 + c0) * 0.1f) * scale;
            float v1 = tanhf((p1 + c1) * 0.1f) * scale;
            float v2 = tanhf((p2 + c2) * 0.1f) * scale;
            g_code[side][row] = make_float4(v0, v1, v2, 0.f);
        }
    }
}

// ---------------------------------------------------------------------------
// Main pass.  out[a,t,s] = x * sigmoid(x/10),  x = Qc(t)·Kc(s)/R.
// |x| < 1  =>  sigmoid(x/10) ~= 0.5 + (x/10)/4 - (x/10)^3/48   (abs err ~2e-8)
// Tile: 8 t-rows x 1024 s-cols per 256-thread block; float4 coalesced stores.
// ---------------------------------------------------------------------------
__device__ __forceinline__ float pc_fn(const float4 q, const float4 k) {
    float x  = fmaf(q.x, k.x, fmaf(q.y, k.y, q.z * k.z));      // Kc already /3
    float t  = x * x;
    float sg = fmaf(x, fmaf(t, -2.0833333e-5f, 0.025f), 0.5f); // sigmoid(x/10)
    return x * sg;
}

__global__ void __launch_bounds__(256) pc_kernel(float* __restrict__ out) {
    const int a     = blockIdx.z;
    const int tbase = blockIdx.y * 8;
    const int sbase = blockIdx.x * 1024;
    const int tid   = threadIdx.x;

    __shared__ float4 kc_sh[1024];
    __shared__ float4 qc_sh[8];

#pragma unroll
    for (int i = 0; i < 4; i++)
        kc_sh[tid + 256 * i] = g_code[0][a * SK_ + sbase + tid + 256 * i];
    if (tid < 8)
        qc_sh[tid] = g_code[1][a * SQ_ + tbase + tid];
    __syncthreads();

    const float4 k0 = kc_sh[tid * 4 + 0];
    const float4 k1 = kc_sh[tid * 4 + 1];
    const float4 k2 = kc_sh[tid * 4 + 2];
    const float4 k3 = kc_sh[tid * 4 + 3];

    size_t obase = ((size_t)(a * SQ_ + tbase)) * SK_ + (size_t)(sbase + tid * 4);
#pragma unroll
    for (int j = 0; j < 8; j++) {
        const float4 q = qc_sh[j];        // broadcast LDS
        float4 o;
        o.x = pc_fn(q, k0);
        o.y = pc_fn(q, k1);
        o.z = pc_fn(q, k2);
        o.w = pc_fn(q, k3);
        *reinterpret_cast<float4*>(out + obase + (size_t)j * SK_) = o;
    }
}

// ---------------------------------------------------------------------------
// Launch
// ---------------------------------------------------------------------------
extern "C" void kernel_launch(void* const* d_in, const int* in_sizes, int n_in,
                              void* d_out, int out_size) {
    const float* K  = (const float*)d_in[0];
    const float* Q  = (const float*)d_in[1];
    const float* Wk = (const float*)d_in[2];
    const float* bk = (const float*)d_in[3];
    const float* Wq = (const float*)d_in[4];
    const float* bq = (const float*)d_in[5];
    const float* W  = (const float*)d_in[6];
    float* out = (float*)d_out;

    fused_code_kernel<<<256, 256>>>(K, Q, Wk, bk, Wq, bq, W);
    pc_kernel<<<dim3(SK_ / 1024, SQ_ / 8, A_), 256>>>(out);
}

// round 6
// speedup vs baseline: 1.3070x; 1.3070x over previous
#include <cuda_runtime.h>
#include <math.h>

// Problem constants (fixed by the dataset)
#define A_   16
#define SK_  2048
#define SQ_  2048
#define D_   128
#define IDM_ 128
#define RR_  3
// T_ANNEAL = 10, t_ANNEAL = 0

// ---------------------------------------------------------------------------
// Scratch (device globals — no allocation allowed)
// ---------------------------------------------------------------------------
__device__ float  g_M[2][A_ * IDM_ * RR_];   // folded projections
__device__ float  g_c[2][A_ * RR_];          // folded bias projections
__device__ float4 g_code[2][A_ * SK_];       // [0] = Kc/3, [1] = Qc

// ---------------------------------------------------------------------------
// Kernel 1 (R2 version): fold Wk/Wq + bias through W[a].
// Grid: 32 blocks = (side, a).  Block: 512 threads = (epart 0..3, d 0..127).
// ---------------------------------------------------------------------------
__global__ void __launch_bounds__(512) prep_kernel(
        const float* __restrict__ Wk, const float* __restrict__ bk,
        const float* __restrict__ Wq, const float* __restrict__ bq,
        const float* __restrict__ W) {
    const int side = blockIdx.x >> 4;        // 0 = K, 1 = Q
    const int a    = blockIdx.x & 15;
    const float* Wx = side ? Wq : Wk;
    const float* bx = side ? bq : bk;

    const int t  = threadIdx.x;
    const int d  = t & 127;
    const int ep = t >> 7;                   // e-partition 0..3

    __shared__ float Wsh[IDM_ * RR_];        // W[a] : [128,3]
    __shared__ float red[4][IDM_ * RR_];     // partial sums

    for (int i = t; i < IDM_ * RR_; i += 512) Wsh[i] = W[a * IDM_ * RR_ + i];
    __syncthreads();

    float a0 = 0.f, a1 = 0.f, a2 = 0.f;
#pragma unroll 8
    for (int i = 0; i < 32; i++) {
        int e = ep * 32 + i;
        float w = Wx[e * D_ + d];
        a0 = fmaf(w, Wsh[e * 3 + 0], a0);
        a1 = fmaf(w, Wsh[e * 3 + 1], a1);
        a2 = fmaf(w, Wsh[e * 3 + 2], a2);
    }
    red[ep][d * 3 + 0] = a0;
    red[ep][d * 3 + 1] = a1;
    red[ep][d * 3 + 2] = a2;
    __syncthreads();

    if (ep == 0) {
        int base = a * (IDM_ * RR_) + d * RR_;
#pragma unroll
        for (int r = 0; r < RR_; r++) {
            int i = d * 3 + r;
            g_M[side][base + r] = red[0][i] + red[1][i] + red[2][i] + red[3][i];
        }
    }

    if (t < 32) {   // bias fold on warp 0
        float c0 = 0.f, c1 = 0.f, c2 = 0.f;
#pragma unroll
        for (int e = t; e < IDM_; e += 32) {
            float b = bx[e];
            c0 = fmaf(b, Wsh[e * 3 + 0], c0);
            c1 = fmaf(b, Wsh[e * 3 + 1], c1);
            c2 = fmaf(b, Wsh[e * 3 + 2], c2);
        }
#pragma unroll
        for (int o = 16; o > 0; o >>= 1) {
            c0 += __shfl_xor_sync(0xffffffffu, c0, o);
            c1 += __shfl_xor_sync(0xffffffffu, c1, o);
            c2 += __shfl_xor_sync(0xffffffffu, c2, o);
        }
        if (t == 0) {
            g_c[side][a * RR_ + 0] = c0;
            g_c[side][a * RR_ + 1] = c1;
            g_c[side][a * RR_ + 2] = c2;
        }
    }
}

// ---------------------------------------------------------------------------
// Kernel 2 (R2 version): hash codes, one warp per sequence row.
// ---------------------------------------------------------------------------
__global__ void code_kernel(const float* __restrict__ K, const float* __restrict__ Q) {
    int warp = (blockIdx.x * blockDim.x + threadIdx.x) >> 5;
    int lane = threadIdx.x & 31;
    int which = (warp >= A_ * SK_) ? 1 : 0;
    int row   = which ? (warp - A_ * SK_) : warp;
    int a     = row >> 11;

    const float* X = which ? Q : K;
    const float4 x = reinterpret_cast<const float4*>(X)[row * (D_ / 4) + lane];

    const float* M = &g_M[which][a * (IDM_ * RR_) + lane * 12];
    float4 m0 = *reinterpret_cast<const float4*>(M);
    float4 m1 = *reinterpret_cast<const float4*>(M + 4);
    float4 m2 = *reinterpret_cast<const float4*>(M + 8);

    float p0 = x.x * m0.x + x.y * m0.w + x.z * m1.z + x.w * m2.y;
    float p1 = x.x * m0.y + x.y * m1.x + x.z * m1.w + x.w * m2.z;
    float p2 = x.x * m0.z + x.y * m1.y + x.z * m2.x + x.w * m2.w;

#pragma unroll
    for (int o = 16; o > 0; o >>= 1) {
        p0 += __shfl_xor_sync(0xffffffffu, p0, o);
        p1 += __shfl_xor_sync(0xffffffffu, p1, o);
        p2 += __shfl_xor_sync(0xffffffffu, p2, o);
    }
    if (lane == 0) {
        const float* c = &g_c[which][a * RR_];
        float scale = which ? 1.0f : (1.0f / 3.0f);
        float v0 = tanhf((p0 + c[0]) * 0.1f) * scale;
        float v1 = tanhf((p1 + c[1]) * 0.1f) * scale;
        float v2 = tanhf((p2 + c[2]) * 0.1f) * scale;
        g_code[which][row] = make_float4(v0, v1, v2, 0.f);
    }
}

// ---------------------------------------------------------------------------
// Kernel 3: main pass, L1-lean version.
// Tile: 16 t-rows x 1024 s-cols per 256-thread block.
// Kc loaded straight to registers (LDG.128, L2-resident); Qc via tiny smem.
// Per warp: 16 LDG-wf + 16 LDS-wf + 64 STG-wf for 64 outputs/thread-row.
// ---------------------------------------------------------------------------
__device__ __forceinline__ float pc_fn(const float4 q, const float4 k) {
    float x  = fmaf(q.x, k.x, fmaf(q.y, k.y, q.z * k.z));      // Kc already /3
    float t  = x * x;
    float sg = fmaf(x, fmaf(t, -2.0833333e-5f, 0.025f), 0.5f); // sigmoid(x/10)
    return x * sg;
}

__global__ void __launch_bounds__(256) pc_kernel(float* __restrict__ out) {
    const int a     = blockIdx.z;
    const int tbase = blockIdx.y * 16;
    const int sbase = blockIdx.x * 1024;
    const int tid   = threadIdx.x;

    __shared__ float4 qc_sh[16];
    if (tid < 16)
        qc_sh[tid] = g_code[1][a * SQ_ + tbase + tid];

    // Kc for this thread's 4 s-positions: direct LDG (hot in L2 across blocks)
    const float4* kc = &g_code[0][a * SK_ + sbase + tid * 4];
    const float4 k0 = kc[0];
    const float4 k1 = kc[1];
    const float4 k2 = kc[2];
    const float4 k3 = kc[3];
    __syncthreads();

    size_t obase = ((size_t)(a * SQ_ + tbase)) * SK_ + (size_t)(sbase + tid * 4);
#pragma unroll
    for (int j = 0; j < 16; j++) {
        const float4 q = qc_sh[j];        // broadcast LDS
        float4 o;
        o.x = pc_fn(q, k0);
        o.y = pc_fn(q, k1);
        o.z = pc_fn(q, k2);
        o.w = pc_fn(q, k3);
        *reinterpret_cast<float4*>(out + obase + (size_t)j * SK_) = o;
    }
}

// ---------------------------------------------------------------------------
// Launch
// ---------------------------------------------------------------------------
extern "C" void kernel_launch(void* const* d_in, const int* in_sizes, int n_in,
                              void* d_out, int out_size) {
    const float* K  = (const float*)d_in[0];
    const float* Q  = (const float*)d_in[1];
    const float* Wk = (const float*)d_in[2];
    const float* bk = (const float*)d_in[3];
    const float* Wq = (const float*)d_in[4];
    const float* bq = (const float*)d_in[5];
    const float* W  = (const float*)d_in[6];
    float* out = (float*)d_out;

    prep_kernel<<<2 * A_, 512>>>(Wk, bk, Wq, bq, W);
    code_kernel<<<(2 * A_ * SK_) / 8, 256>>>(K, Q);
    pc_kernel<<<dim3(SK_ / 1024, SQ_ / 16, A_), 256>>>(out);
}